// round 3
// baseline (speedup 1.0000x reference)
#include <cuda_runtime.h>
#include <cstdint>
#include <cstddef>

// ---------------------------------------------------------------------------
// ParallelMoELinear: out[t,:] = tokens[t,:] @ W[e(t)] + bias[e(t)]
// E=8, T=4096, D_IN=1024, D_OUT=4096, 512 tokens/expert (sorted).
// sm_100 (no 'a'): legacy tensor core path, mma.sync.m16n8k8.tf32 + RN cvt.
// R3: 16 warps/CTA (4 per SMSP) + 4-stage cp.async pipeline to fix the
// latency-hiding problem seen in R2 (tensor 43%, issue 34%, occ 12%).
// ---------------------------------------------------------------------------
static constexpr int D_IN  = 1024;
static constexpr int D_OUT = 4096;
static constexpr int T_TOK = 4096;

static constexpr int BM = 128;
static constexpr int BN = 128;
static constexpr int BK = 32;
static constexpr int NSTAGE = 4;
static constexpr int NKT = D_IN / BK;       // 32 k-tiles
static constexpr int NTHREADS = 512;        // 16 warps: 4 in M x 4 in N

// SMEM geometry (word = 4B):
//  A tile: [BM][AROW_W], AROW_W = 36 (32 data + 4 pad)
//    -> LDSM row stride 144B == 4 mod 32 words: conflict-free.
//  B tile: [BK][BROW_W], BROW_W = 136 (128 data + 8 pad)
//    -> scalar B-frag banks = 8*(lane%4) + lane/4: all 32 distinct.
static constexpr int AROW_W = 36;
static constexpr int BROW_W = 136;
static constexpr uint32_t A_STAGE_B = BM * AROW_W * 4;        // 18432
static constexpr uint32_t B_STAGE_B = BK * BROW_W * 4;        // 17408
static constexpr uint32_t SMEM_B0   = NSTAGE * A_STAGE_B;     // 73728
static constexpr uint32_t SMEM_TOTAL = SMEM_B0 + NSTAGE * B_STAGE_B; // 143360

// ---------------------------------------------------------------------------
// PTX helpers (sm_80+)
// ---------------------------------------------------------------------------
__device__ __forceinline__ uint32_t smem_to_u32(const void* p) {
    uint32_t a;
    asm("{ .reg .u64 t; cvta.to.shared.u64 t, %1; cvt.u32.u64 %0, t; }"
        : "=r"(a) : "l"(p));
    return a;
}

#define CP_ASYNC_16(dst, src) \
    asm volatile("cp.async.cg.shared.global [%0], [%1], 16;" \
        :: "r"(dst), "l"(src) : "memory")
#define CP_ASYNC_COMMIT() \
    asm volatile("cp.async.commit_group;" ::: "memory")
#define CP_ASYNC_WAIT_GROUP(n) \
    asm volatile("cp.async.wait_group %0;" :: "n"(n) : "memory")

#define LDSM_X4(r, addr) \
    asm volatile("ldmatrix.sync.aligned.m8n8.x4.shared.b16 {%0,%1,%2,%3}, [%4];" \
        : "=r"((r)[0]), "=r"((r)[1]), "=r"((r)[2]), "=r"((r)[3]) \
        : "r"(addr))

#define LDS32(r, addr) \
    asm volatile("ld.shared.b32 %0, [%1];" : "=r"(r) : "r"(addr))

// fp32 -> tf32 round-to-nearest. Truncation (raw fp32 into the MMA) would
// bias every dot product low by ~1e-3 rel; RN keeps it zero-mean (~3e-4).
#define CVT_TF32(x) asm volatile("cvt.rna.tf32.f32 %0, %0;" : "+r"(x))

#define MMA_TF32(d, a, b) \
    asm volatile( \
        "mma.sync.aligned.m16n8k8.row.col.f32.tf32.tf32.f32 " \
        "{%0,%1,%2,%3}, {%4,%5,%6,%7}, {%8,%9}, {%0,%1,%2,%3};" \
        : "+f"((d)[0]), "+f"((d)[1]), "+f"((d)[2]), "+f"((d)[3]) \
        : "r"((a)[0]), "r"((a)[1]), "r"((a)[2]), "r"((a)[3]), \
          "r"((b)[0]), "r"((b)[1]))

// ---------------------------------------------------------------------------
// Kernel
// ---------------------------------------------------------------------------
__global__ void __launch_bounds__(NTHREADS, 1)
moe_tf32_mma_kernel(const float* __restrict__ tokens,
                    const float* __restrict__ W,
                    const float* __restrict__ bias,
                    const int* __restrict__ experts,
                    float* __restrict__ out) {
    extern __shared__ char smem[];
    const uint32_t sb = smem_to_u32(smem);

    const int tid  = threadIdx.x;
    const int lane = tid & 31;
    const int wid  = tid >> 5;
    const int warp_m = wid & 3;       // 4 warps in M -> 32-row warp tiles
    const int warp_n = wid >> 2;      // 4 warps in N -> 32-col warp tiles

    const int m_base = blockIdx.y * BM;
    const int n_base = blockIdx.x * BN;
    const int e = experts[m_base];    // uniform within 128-row tile (128 | 512)

    const float* Ag = tokens + (size_t)m_base * D_IN;
    const float* Bg = W + (size_t)e * D_IN * D_OUT + n_base;

    // ldmatrix per-thread offset (proven mapping from R2):
    //  lanes 0-7: rows 0-7 k-blk 0 | 8-15: rows 8-15 blk 0 |
    //  16-23: rows 0-7 blk 1 (+16B) | 24-31: rows 8-15 blk 1
    const uint32_t a_toff =
        (uint32_t)(((lane & 7) + ((lane >> 3) & 1) * 8) * (AROW_W * 4) +
                   (lane >> 4) * 16);
    // B scalar fragment: b0 = Bs[k = lane%4][n = lane/4]
    const uint32_t b_toff =
        (uint32_t)((lane & 3) * (BROW_W * 4) + (lane >> 2) * 4);

    float acc[2][4][4];
#pragma unroll
    for (int i = 0; i < 2; i++)
#pragma unroll
        for (int j = 0; j < 4; j++)
#pragma unroll
            for (int q = 0; q < 4; q++) acc[i][j][q] = 0.0f;

    // ---- stage loader: 512 threads, 2 x 16B ops each for A and for B ----
    auto load_stage = [&](int st, int kt) {
        const uint32_t as = sb + (uint32_t)st * A_STAGE_B;
        const uint32_t bs = sb + SMEM_B0 + (uint32_t)st * B_STAGE_B;
        const float* ag = Ag + kt * BK;
        const float* bg = Bg + (size_t)kt * BK * D_OUT;
#pragma unroll
        for (int i = 0; i < 2; i++) {
            int id = tid + i * NTHREADS;        // 0..1023
            int u = id & 7, r = id >> 3;
            CP_ASYNC_16(as + (uint32_t)(r * (AROW_W * 4) + u * 16),
                        ag + (size_t)r * D_IN + u * 4);
        }
#pragma unroll
        for (int i = 0; i < 2; i++) {
            int id = tid + i * NTHREADS;
            int nu = id & 31, k = id >> 5;
            CP_ASYNC_16(bs + (uint32_t)(k * (BROW_W * 4) + nu * 16),
                        bg + (size_t)k * D_OUT + nu * 4);
        }
    };

    // Prologue: 3 stages in flight.
    load_stage(0, 0); CP_ASYNC_COMMIT();
    load_stage(1, 1); CP_ASYNC_COMMIT();
    load_stage(2, 2); CP_ASYNC_COMMIT();

    // ---- mainloop ----
    for (int i = 0; i < NKT; i++) {
        // Ensure group i is complete (groups retire in order).
        if (i < NKT - 2)       { CP_ASYNC_WAIT_GROUP(2); }
        else if (i == NKT - 2) { CP_ASYNC_WAIT_GROUP(1); }
        else                   { CP_ASYNC_WAIT_GROUP(0); }
        __syncthreads();

        if (i + 3 < NKT) {
            load_stage((i + 3) % NSTAGE, i + 3);
            CP_ASYNC_COMMIT();
        }

        const int st = i % NSTAGE;
        const uint32_t abase = sb + (uint32_t)st * A_STAGE_B +
                               (uint32_t)(warp_m * 32 * (AROW_W * 4)) + a_toff;
        const uint32_t bbase = sb + SMEM_B0 + (uint32_t)st * B_STAGE_B +
                               (uint32_t)(warp_n * 32 * 4) + b_toff;

#pragma unroll
        for (int s = 0; s < BK / 8; s++) {          // 4 k-steps of 8
            uint32_t a[2][4];
#pragma unroll
            for (int im = 0; im < 2; im++) {
                LDSM_X4(a[im], abase + (uint32_t)(im * 16 * (AROW_W * 4) + s * 32));
#pragma unroll
                for (int q = 0; q < 4; q++) CVT_TF32(a[im][q]);
            }
            uint32_t b[4][2];
#pragma unroll
            for (int jn = 0; jn < 4; jn++) {
                const uint32_t ba = bbase + (uint32_t)(jn * 32 + s * 8 * (BROW_W * 4));
                LDS32(b[jn][0], ba);
                LDS32(b[jn][1], ba + 4 * (BROW_W * 4));
                CVT_TF32(b[jn][0]);
                CVT_TF32(b[jn][1]);
            }
#pragma unroll
            for (int im = 0; im < 2; im++)
#pragma unroll
                for (int jn = 0; jn < 4; jn++)
                    MMA_TF32(acc[im][jn], a[im], b[jn]);
        }
    }

    // ---- epilogue: add bias, store float2 pairs ----
    const float* be = bias + (size_t)e * D_OUT + n_base + warp_n * 32;
    const int row0 = m_base + warp_m * 32 + (lane >> 2);
    const int col0 = n_base + warp_n * 32 + (lane & 3) * 2;

#pragma unroll
    for (int jn = 0; jn < 4; jn++) {
        const float2 bb = *reinterpret_cast<const float2*>(be + jn * 8 + (lane & 3) * 2);
#pragma unroll
        for (int im = 0; im < 2; im++) {
            const int r = row0 + im * 16;
            float2 v0 = make_float2(acc[im][jn][0] + bb.x, acc[im][jn][1] + bb.y);
            float2 v1 = make_float2(acc[im][jn][2] + bb.x, acc[im][jn][3] + bb.y);
            *reinterpret_cast<float2*>(out + (size_t)r * D_OUT + col0 + jn * 8) = v0;
            *reinterpret_cast<float2*>(out + (size_t)(r + 8) * D_OUT + col0 + jn * 8) = v1;
        }
    }
}

// ---------------------------------------------------------------------------
// Launch. Inputs (metadata order): sorted_tokens f32[4096,1024],
// kernel f32[8,1024,4096], bias f32[8,4096], group_sizes i32[8],
// sorted_experts i32[4096]. Output f32[4096,4096].
// ---------------------------------------------------------------------------
extern "C" void kernel_launch(void* const* d_in, const int* in_sizes, int n_in,
                              void* d_out, int out_size) {
    const float* tokens  = (const float*)d_in[0];
    const float* W       = (const float*)d_in[1];
    const float* bias    = (const float*)d_in[2];
    const int*   experts = (const int*)d_in[4];   // d_in[3] = group_sizes (unused)
    float* out = (float*)d_out;

    cudaFuncSetAttribute(moe_tf32_mma_kernel,
                         cudaFuncAttributeMaxDynamicSharedMemorySize, SMEM_TOTAL);

    dim3 grid(D_OUT / BN, T_TOK / BM);   // (32, 32)
    moe_tf32_mma_kernel<<<grid, NTHREADS, SMEM_TOTAL>>>(tokens, W, bias, experts, out);
}

// round 4
// speedup vs baseline: 1.1450x; 1.1450x over previous
#include <cuda_runtime.h>
#include <cstdint>
#include <cstddef>

// ---------------------------------------------------------------------------
// ParallelMoELinear: out[t,:] = tokens[t,:] @ W[e(t)] + bias[e(t)]
// E=8, T=4096, D_IN=1024, D_OUT=4096, 512 tokens/expert (sorted).
// sm_100 legacy tensor path (tcgen05 unavailable at this compile target).
// R4: zero CVTs in the mainloop. A is pre-rounded to tf32 (RN) by a prepass
// kernel into a __device__ scratch (with a +3.38e-4 scale to cancel the mean
// truncation bias the MMA applies to raw-fp32 W). W is truncated in-HW.
// ---------------------------------------------------------------------------
static constexpr int D_IN  = 1024;
static constexpr int D_OUT = 4096;
static constexpr int T_TOK = 4096;

static constexpr int BM = 128;
static constexpr int BN = 128;
static constexpr int BK = 32;
static constexpr int NSTAGE = 4;
static constexpr int NKT = D_IN / BK;       // 32
static constexpr int NTHREADS = 256;        // 8 warps: 2 (M) x 4 (N), 64x32 warp tiles

// SMEM geometry (word = 4B):
//  A tile: [BM][AROW_W], AROW_W = 36 (32 data + 4 pad)
//    -> LDSM row stride 144B == 4 mod 32 words: conflict-free ldmatrix.
//  B tile: [BK][BROW_W], BROW_W = 136 (128 data + 8 pad)
//    -> scalar B-frag banks = 8*(lane%4) + lane/4: all 32 distinct.
static constexpr int AROW_W = 36;
static constexpr int BROW_W = 136;
static constexpr uint32_t A_STAGE_B = BM * AROW_W * 4;        // 18432
static constexpr uint32_t B_STAGE_B = BK * BROW_W * 4;        // 17408
static constexpr uint32_t SMEM_B0   = NSTAGE * A_STAGE_B;     // 73728
static constexpr uint32_t SMEM_TOTAL = SMEM_B0 + NSTAGE * B_STAGE_B; // 143360

// Scratch for pre-rounded A (16 MB). Device-global scratch is the sanctioned
// way to get workspace without allocating.
__device__ float g_a_tf32[(size_t)T_TOK * D_IN];

// ---------------------------------------------------------------------------
// PTX helpers (sm_80+)
// ---------------------------------------------------------------------------
__device__ __forceinline__ uint32_t smem_to_u32(const void* p) {
    uint32_t a;
    asm("{ .reg .u64 t; cvta.to.shared.u64 t, %1; cvt.u32.u64 %0, t; }"
        : "=r"(a) : "l"(p));
    return a;
}

#define CP_ASYNC_16(dst, src) \
    asm volatile("cp.async.cg.shared.global [%0], [%1], 16;" \
        :: "r"(dst), "l"(src) : "memory")
#define CP_ASYNC_COMMIT() \
    asm volatile("cp.async.commit_group;" ::: "memory")
#define CP_ASYNC_WAIT_GROUP(n) \
    asm volatile("cp.async.wait_group %0;" :: "n"(n) : "memory")

#define LDSM_X4(r, addr) \
    asm volatile("ldmatrix.sync.aligned.m8n8.x4.shared.b16 {%0,%1,%2,%3}, [%4];" \
        : "=r"((r)[0]), "=r"((r)[1]), "=r"((r)[2]), "=r"((r)[3]) \
        : "r"(addr))

#define LDS32(r, addr) \
    asm volatile("ld.shared.b32 %0, [%1];" : "=r"(r) : "r"(addr))

#define CVT_TF32(x) asm volatile("cvt.rna.tf32.f32 %0, %0;" : "+r"(x))

#define MMA_TF32(d, a, b) \
    asm volatile( \
        "mma.sync.aligned.m16n8k8.row.col.f32.tf32.tf32.f32 " \
        "{%0,%1,%2,%3}, {%4,%5,%6,%7}, {%8,%9}, {%0,%1,%2,%3};" \
        : "+f"((d)[0]), "+f"((d)[1]), "+f"((d)[2]), "+f"((d)[3]) \
        : "r"((a)[0]), "r"((a)[1]), "r"((a)[2]), "r"((a)[3]), \
          "r"((b)[0]), "r"((b)[1]))

// ---------------------------------------------------------------------------
// Prepass: A -> tf32(RN), scaled by (1 + 2^-11*ln2) to cancel the deterministic
// downward bias from HW truncation of raw-fp32 W inside the MMA.
// ---------------------------------------------------------------------------
__global__ void __launch_bounds__(256)
a_round_kernel(const float* __restrict__ a_in) {
    const size_t i = ((size_t)blockIdx.x * 256 + threadIdx.x) * 4;
    float4 v = *reinterpret_cast<const float4*>(a_in + i);
    const float s = 1.000338f;
    uint32_t x0 = __float_as_uint(v.x * s);
    uint32_t x1 = __float_as_uint(v.y * s);
    uint32_t x2 = __float_as_uint(v.z * s);
    uint32_t x3 = __float_as_uint(v.w * s);
    CVT_TF32(x0); CVT_TF32(x1); CVT_TF32(x2); CVT_TF32(x3);
    float4 o;
    o.x = __uint_as_float(x0); o.y = __uint_as_float(x1);
    o.z = __uint_as_float(x2); o.w = __uint_as_float(x3);
    *reinterpret_cast<float4*>(g_a_tf32 + i) = o;
}

// ---------------------------------------------------------------------------
// GEMM kernel
// ---------------------------------------------------------------------------
__global__ void __launch_bounds__(NTHREADS, 1)
moe_tf32_mma_kernel(const float* __restrict__ W,
                    const float* __restrict__ bias,
                    const int* __restrict__ experts,
                    float* __restrict__ out) {
    extern __shared__ char smem[];
    const uint32_t sb = smem_to_u32(smem);

    const int tid  = threadIdx.x;
    const int lane = tid & 31;
    const int wid  = tid >> 5;
    const int warp_m = wid & 1;       // 2 warps in M -> 64-row warp tiles
    const int warp_n = wid >> 1;      // 4 warps in N -> 32-col warp tiles

    const int m_base = blockIdx.y * BM;
    const int n_base = blockIdx.x * BN;
    const int e = experts[m_base];    // uniform within 128-row tile (128 | 512)

    // ---- per-thread cp.async source pointers (advance by constants) ----
    // A: 1024 16B ops/stage; thread does ids {tid, tid+256, tid+512, tid+768}
    //    id -> (row = id>>3, unit = id&7)
    // B: same count; id -> (k = id>>5, nunit = id&31)
    const float* a_src = g_a_tf32 + (size_t)m_base * D_IN +
                         (size_t)(tid >> 3) * D_IN + (tid & 7) * 4;
    const float* b_src = W + (size_t)e * D_IN * D_OUT + n_base +
                         (size_t)(tid >> 5) * D_OUT + (tid & 31) * 4;
    // matching SMEM destination offsets (within a stage)
    const uint32_t a_dst = (uint32_t)((tid >> 3) * (AROW_W * 4) + (tid & 7) * 16);
    const uint32_t b_dst = (uint32_t)((tid >> 5) * (BROW_W * 4) + (tid & 31) * 16);
    // strides between the 4 ops of one thread (id += 256)
    static constexpr int A_GSTRIDE = 32 * D_IN;          // 32 rows
    static constexpr uint32_t A_SSTRIDE = 32 * AROW_W * 4;
    static constexpr int B_GSTRIDE = 8 * D_OUT;          // 8 k-rows
    static constexpr uint32_t B_SSTRIDE = 8 * BROW_W * 4;

    // ldmatrix per-thread offset (proven mapping):
    const uint32_t a_toff =
        (uint32_t)(((lane & 7) + ((lane >> 3) & 1) * 8) * (AROW_W * 4) +
                   (lane >> 4) * 16);
    // B scalar fragment: b0 = Bs[k = lane%4][n = lane/4]
    const uint32_t b_toff =
        (uint32_t)((lane & 3) * (BROW_W * 4) + (lane >> 2) * 4);

    float acc[4][4][4];
#pragma unroll
    for (int i = 0; i < 4; i++)
#pragma unroll
        for (int j = 0; j < 4; j++)
#pragma unroll
            for (int q = 0; q < 4; q++) acc[i][j][q] = 0.0f;

    auto load_stage = [&](int st, int kt) {
        const uint32_t as = sb + (uint32_t)st * A_STAGE_B + a_dst;
        const uint32_t bs = sb + SMEM_B0 + (uint32_t)st * B_STAGE_B + b_dst;
        const float* ag = a_src + kt * BK;
        const float* bg = b_src + (size_t)kt * BK * D_OUT;
#pragma unroll
        for (int i = 0; i < 4; i++)
            CP_ASYNC_16(as + (uint32_t)i * A_SSTRIDE, ag + (size_t)i * A_GSTRIDE);
#pragma unroll
        for (int i = 0; i < 4; i++)
            CP_ASYNC_16(bs + (uint32_t)i * B_SSTRIDE, bg + (size_t)i * B_GSTRIDE);
    };

    // Prologue: 3 stages in flight.
    load_stage(0, 0); CP_ASYNC_COMMIT();
    load_stage(1, 1); CP_ASYNC_COMMIT();
    load_stage(2, 2); CP_ASYNC_COMMIT();

    // ---- mainloop ----
    for (int i = 0; i < NKT; i++) {
        if (i < NKT - 2)       { CP_ASYNC_WAIT_GROUP(2); }
        else if (i == NKT - 2) { CP_ASYNC_WAIT_GROUP(1); }
        else                   { CP_ASYNC_WAIT_GROUP(0); }
        __syncthreads();

        if (i + 3 < NKT) {
            load_stage((i + 3) % NSTAGE, i + 3);
            CP_ASYNC_COMMIT();
        }

        const int st = i % NSTAGE;
        const uint32_t abase = sb + (uint32_t)st * A_STAGE_B +
                               (uint32_t)(warp_m * 64 * (AROW_W * 4)) + a_toff;
        const uint32_t bbase = sb + SMEM_B0 + (uint32_t)st * B_STAGE_B +
                               (uint32_t)(warp_n * 32 * 4) + b_toff;

#pragma unroll
        for (int s = 0; s < BK / 8; s++) {          // 4 k-steps of 8
            uint32_t a[4][4];
#pragma unroll
            for (int im = 0; im < 4; im++)
                LDSM_X4(a[im], abase + (uint32_t)(im * 16 * (AROW_W * 4) + s * 32));
            uint32_t b[4][2];
#pragma unroll
            for (int jn = 0; jn < 4; jn++) {
                const uint32_t ba = bbase + (uint32_t)(jn * 32 + s * 8 * (BROW_W * 4));
                LDS32(b[jn][0], ba);
                LDS32(b[jn][1], ba + 4 * (BROW_W * 4));
            }
#pragma unroll
            for (int im = 0; im < 4; im++)
#pragma unroll
                for (int jn = 0; jn < 4; jn++)
                    MMA_TF32(acc[im][jn], a[im], b[jn]);
        }
    }

    // ---- epilogue: add bias, store float2 pairs ----
    const float* be = bias + (size_t)e * D_OUT + n_base + warp_n * 32;
    const int row0 = m_base + warp_m * 64 + (lane >> 2);
    const int col0 = n_base + warp_n * 32 + (lane & 3) * 2;

#pragma unroll
    for (int jn = 0; jn < 4; jn++) {
        const float2 bb = *reinterpret_cast<const float2*>(be + jn * 8 + (lane & 3) * 2);
#pragma unroll
        for (int im = 0; im < 4; im++) {
            const int r = row0 + im * 16;
            float2 v0 = make_float2(acc[im][jn][0] + bb.x, acc[im][jn][1] + bb.y);
            float2 v1 = make_float2(acc[im][jn][2] + bb.x, acc[im][jn][3] + bb.y);
            *reinterpret_cast<float2*>(out + (size_t)r * D_OUT + col0 + jn * 8) = v0;
            *reinterpret_cast<float2*>(out + (size_t)(r + 8) * D_OUT + col0 + jn * 8) = v1;
        }
    }
}

// ---------------------------------------------------------------------------
// Launch. Inputs (metadata order): sorted_tokens f32[4096,1024],
// kernel f32[8,1024,4096], bias f32[8,4096], group_sizes i32[8],
// sorted_experts i32[4096]. Output f32[4096,4096].
// ---------------------------------------------------------------------------
extern "C" void kernel_launch(void* const* d_in, const int* in_sizes, int n_in,
                              void* d_out, int out_size) {
    const float* tokens  = (const float*)d_in[0];
    const float* W       = (const float*)d_in[1];
    const float* bias    = (const float*)d_in[2];
    const int*   experts = (const int*)d_in[4];   // d_in[3] = group_sizes (unused)
    float* out = (float*)d_out;

    // Prepass: 4M floats, one float4 per thread.
    a_round_kernel<<<(T_TOK * D_IN) / (256 * 4), 256>>>(tokens);

    cudaFuncSetAttribute(moe_tf32_mma_kernel,
                         cudaFuncAttributeMaxDynamicSharedMemorySize, SMEM_TOTAL);
    dim3 grid(D_OUT / BN, T_TOK / BM);   // (32, 32)
    moe_tf32_mma_kernel<<<grid, NTHREADS, SMEM_TOTAL>>>(W, bias, experts, out);
}

// round 5
// speedup vs baseline: 1.3490x; 1.1781x over previous
#include <cuda_runtime.h>
#include <cstdint>
#include <cstddef>

// ---------------------------------------------------------------------------
// ParallelMoELinear: out[t,:] = tokens[t,:] @ W[e(t)] + bias[e(t)]
// E=8, T=4096, D_IN=1024, D_OUT=4096, 512 tokens/expert (sorted).
// sm_100 legacy tensor path (tcgen05 unavailable at this compile target).
// R5: 2 CTAs/SM. R4 showed a ~1000 cyc/iter per-CTA bubble (sync + LDSM ramp)
// that a single resident CTA cannot cover (tensor pinned at 49%). 3-stage
// pipeline shrinks SMEM to 107.5KB so two CTAs co-reside; their barriers are
// independent, so one CTA's HMMAs cover the other's bubble.
// A is pre-rounded to tf32(RN) with a +3.38e-4 scale that cancels the mean
// truncation bias of raw-fp32 W inside the MMA (validated R4: rel_err 3.0e-4).
// ---------------------------------------------------------------------------
static constexpr int D_IN  = 1024;
static constexpr int D_OUT = 4096;
static constexpr int T_TOK = 4096;

static constexpr int BM = 128;
static constexpr int BN = 128;
static constexpr int BK = 32;
static constexpr int NSTAGE = 3;
static constexpr int NKT = D_IN / BK;       // 32
static constexpr int NTHREADS = 256;        // 8 warps: 2 (M) x 4 (N), 64x32 warp tiles

// SMEM geometry (word = 4B):
//  A tile: [BM][AROW_W], AROW_W = 36 (32 data + 4 pad)
//    -> LDSM row stride 144B == 4 mod 32 words: conflict-free ldmatrix.
//  B tile: [BK][BROW_W], BROW_W = 136 (128 data + 8 pad)
//    -> scalar B-frag banks = 8*(lane%4) + lane/4: all 32 distinct.
static constexpr int AROW_W = 36;
static constexpr int BROW_W = 136;
static constexpr uint32_t A_STAGE_B = BM * AROW_W * 4;        // 18432
static constexpr uint32_t B_STAGE_B = BK * BROW_W * 4;        // 17408
static constexpr uint32_t SMEM_B0   = NSTAGE * A_STAGE_B;     // 55296
static constexpr uint32_t SMEM_TOTAL = SMEM_B0 + NSTAGE * B_STAGE_B; // 107520

// Scratch for pre-rounded A (16 MB).
__device__ float g_a_tf32[(size_t)T_TOK * D_IN];

// ---------------------------------------------------------------------------
// PTX helpers (sm_80+)
// ---------------------------------------------------------------------------
__device__ __forceinline__ uint32_t smem_to_u32(const void* p) {
    uint32_t a;
    asm("{ .reg .u64 t; cvta.to.shared.u64 t, %1; cvt.u32.u64 %0, t; }"
        : "=r"(a) : "l"(p));
    return a;
}

#define CP_ASYNC_16(dst, src) \
    asm volatile("cp.async.cg.shared.global [%0], [%1], 16;" \
        :: "r"(dst), "l"(src) : "memory")
#define CP_ASYNC_COMMIT() \
    asm volatile("cp.async.commit_group;" ::: "memory")
#define CP_ASYNC_WAIT_GROUP(n) \
    asm volatile("cp.async.wait_group %0;" :: "n"(n) : "memory")

#define LDSM_X4(r, addr) \
    asm volatile("ldmatrix.sync.aligned.m8n8.x4.shared.b16 {%0,%1,%2,%3}, [%4];" \
        : "=r"((r)[0]), "=r"((r)[1]), "=r"((r)[2]), "=r"((r)[3]) \
        : "r"(addr))

#define LDS32(r, addr) \
    asm volatile("ld.shared.b32 %0, [%1];" : "=r"(r) : "r"(addr))

#define CVT_TF32(x) asm volatile("cvt.rna.tf32.f32 %0, %0;" : "+r"(x))

#define MMA_TF32(d, a, b) \
    asm volatile( \
        "mma.sync.aligned.m16n8k8.row.col.f32.tf32.tf32.f32 " \
        "{%0,%1,%2,%3}, {%4,%5,%6,%7}, {%8,%9}, {%0,%1,%2,%3};" \
        : "+f"((d)[0]), "+f"((d)[1]), "+f"((d)[2]), "+f"((d)[3]) \
        : "r"((a)[0]), "r"((a)[1]), "r"((a)[2]), "r"((a)[3]), \
          "r"((b)[0]), "r"((b)[1]))

// ---------------------------------------------------------------------------
// Prepass: A -> tf32(RN) * (1 + 2^-11*ln2), cancels W-truncation bias.
// ---------------------------------------------------------------------------
__global__ void __launch_bounds__(256)
a_round_kernel(const float* __restrict__ a_in) {
    const size_t i = ((size_t)blockIdx.x * 256 + threadIdx.x) * 4;
    float4 v = *reinterpret_cast<const float4*>(a_in + i);
    const float s = 1.000338f;
    uint32_t x0 = __float_as_uint(v.x * s);
    uint32_t x1 = __float_as_uint(v.y * s);
    uint32_t x2 = __float_as_uint(v.z * s);
    uint32_t x3 = __float_as_uint(v.w * s);
    CVT_TF32(x0); CVT_TF32(x1); CVT_TF32(x2); CVT_TF32(x3);
    float4 o;
    o.x = __uint_as_float(x0); o.y = __uint_as_float(x1);
    o.z = __uint_as_float(x2); o.w = __uint_as_float(x3);
    *reinterpret_cast<float4*>(g_a_tf32 + i) = o;
}

// ---------------------------------------------------------------------------
// GEMM kernel
// ---------------------------------------------------------------------------
__global__ void __launch_bounds__(NTHREADS, 2)
moe_tf32_mma_kernel(const float* __restrict__ W,
                    const float* __restrict__ bias,
                    const int* __restrict__ experts,
                    float* __restrict__ out) {
    extern __shared__ char smem[];
    const uint32_t sb = smem_to_u32(smem);

    const int tid  = threadIdx.x;
    const int lane = tid & 31;
    const int wid  = tid >> 5;
    const int warp_m = wid & 1;       // 2 warps in M -> 64-row warp tiles
    const int warp_n = wid >> 1;      // 4 warps in N -> 32-col warp tiles

    const int m_base = blockIdx.y * BM;
    const int n_base = blockIdx.x * BN;
    const int e = experts[m_base];    // uniform within 128-row tile (128 | 512)

    // per-thread cp.async source/dest (advance by constants)
    const float* a_src = g_a_tf32 + (size_t)m_base * D_IN +
                         (size_t)(tid >> 3) * D_IN + (tid & 7) * 4;
    const float* b_src = W + (size_t)e * D_IN * D_OUT + n_base +
                         (size_t)(tid >> 5) * D_OUT + (tid & 31) * 4;
    const uint32_t a_dst = (uint32_t)((tid >> 3) * (AROW_W * 4) + (tid & 7) * 16);
    const uint32_t b_dst = (uint32_t)((tid >> 5) * (BROW_W * 4) + (tid & 31) * 16);
    static constexpr int A_GSTRIDE = 32 * D_IN;          // 32 rows
    static constexpr uint32_t A_SSTRIDE = 32 * AROW_W * 4;
    static constexpr int B_GSTRIDE = 8 * D_OUT;          // 8 k-rows
    static constexpr uint32_t B_SSTRIDE = 8 * BROW_W * 4;

    // ldmatrix per-thread offset (proven mapping)
    const uint32_t a_toff =
        (uint32_t)(((lane & 7) + ((lane >> 3) & 1) * 8) * (AROW_W * 4) +
                   (lane >> 4) * 16);
    // B scalar fragment: b0 = Bs[k = lane%4][n = lane/4]
    const uint32_t b_toff =
        (uint32_t)((lane & 3) * (BROW_W * 4) + (lane >> 2) * 4);

    float acc[4][4][4];
#pragma unroll
    for (int i = 0; i < 4; i++)
#pragma unroll
        for (int j = 0; j < 4; j++)
#pragma unroll
            for (int q = 0; q < 4; q++) acc[i][j][q] = 0.0f;

    auto load_stage = [&](int st, int kt) {
        const uint32_t as = sb + (uint32_t)st * A_STAGE_B + a_dst;
        const uint32_t bs = sb + SMEM_B0 + (uint32_t)st * B_STAGE_B + b_dst;
        const float* ag = a_src + kt * BK;
        const float* bg = b_src + (size_t)kt * BK * D_OUT;
#pragma unroll
        for (int i = 0; i < 4; i++)
            CP_ASYNC_16(as + (uint32_t)i * A_SSTRIDE, ag + (size_t)i * A_GSTRIDE);
#pragma unroll
        for (int i = 0; i < 4; i++)
            CP_ASYNC_16(bs + (uint32_t)i * B_SSTRIDE, bg + (size_t)i * B_GSTRIDE);
    };

    // Prologue: 2 stages in flight.
    load_stage(0, 0); CP_ASYNC_COMMIT();
    load_stage(1, 1); CP_ASYNC_COMMIT();

    // ---- mainloop ----
    for (int i = 0; i < NKT; i++) {
        // Group i must be complete. Steady state: 2 groups pending -> wait(1).
        if (i < NKT - 1) { CP_ASYNC_WAIT_GROUP(1); } else { CP_ASYNC_WAIT_GROUP(0); }
        __syncthreads();

        if (i + 2 < NKT) {
            load_stage((i + 2) % NSTAGE, i + 2);
            CP_ASYNC_COMMIT();
        }

        const int st = i % NSTAGE;
        const uint32_t abase = sb + (uint32_t)st * A_STAGE_B +
                               (uint32_t)(warp_m * 64 * (AROW_W * 4)) + a_toff;
        const uint32_t bbase = sb + SMEM_B0 + (uint32_t)st * B_STAGE_B +
                               (uint32_t)(warp_n * 32 * 4) + b_toff;

#pragma unroll
        for (int s = 0; s < BK / 8; s++) {          // 4 k-steps of 8
            uint32_t a[4][4];
#pragma unroll
            for (int im = 0; im < 4; im++)
                LDSM_X4(a[im], abase + (uint32_t)(im * 16 * (AROW_W * 4) + s * 32));
            uint32_t b[4][2];
#pragma unroll
            for (int jn = 0; jn < 4; jn++) {
                const uint32_t ba = bbase + (uint32_t)(jn * 32 + s * 8 * (BROW_W * 4));
                LDS32(b[jn][0], ba);
                LDS32(b[jn][1], ba + 4 * (BROW_W * 4));
            }
#pragma unroll
            for (int im = 0; im < 4; im++)
#pragma unroll
                for (int jn = 0; jn < 4; jn++)
                    MMA_TF32(acc[im][jn], a[im], b[jn]);
        }
    }

    // ---- epilogue: add bias, store float2 pairs ----
    const float* be = bias + (size_t)e * D_OUT + n_base + warp_n * 32;
    const int row0 = m_base + warp_m * 64 + (lane >> 2);
    const int col0 = n_base + warp_n * 32 + (lane & 3) * 2;

#pragma unroll
    for (int jn = 0; jn < 4; jn++) {
        const float2 bb = *reinterpret_cast<const float2*>(be + jn * 8 + (lane & 3) * 2);
#pragma unroll
        for (int im = 0; im < 4; im++) {
            const int r = row0 + im * 16;
            float2 v0 = make_float2(acc[im][jn][0] + bb.x, acc[im][jn][1] + bb.y);
            float2 v1 = make_float2(acc[im][jn][2] + bb.x, acc[im][jn][3] + bb.y);
            *reinterpret_cast<float2*>(out + (size_t)r * D_OUT + col0 + jn * 8) = v0;
            *reinterpret_cast<float2*>(out + (size_t)(r + 8) * D_OUT + col0 + jn * 8) = v1;
        }
    }
}

// ---------------------------------------------------------------------------
// Launch. Inputs (metadata order): sorted_tokens f32[4096,1024],
// kernel f32[8,1024,4096], bias f32[8,4096], group_sizes i32[8],
// sorted_experts i32[4096]. Output f32[4096,4096].
// ---------------------------------------------------------------------------
extern "C" void kernel_launch(void* const* d_in, const int* in_sizes, int n_in,
                              void* d_out, int out_size) {
    const float* tokens  = (const float*)d_in[0];
    const float* W       = (const float*)d_in[1];
    const float* bias    = (const float*)d_in[2];
    const int*   experts = (const int*)d_in[4];   // d_in[3] = group_sizes (unused)
    float* out = (float*)d_out;

    // Prepass: 4M floats, one float4 per thread.
    a_round_kernel<<<(T_TOK * D_IN) / (256 * 4), 256>>>(tokens);

    cudaFuncSetAttribute(moe_tf32_mma_kernel,
                         cudaFuncAttributeMaxDynamicSharedMemorySize, SMEM_TOTAL);
    dim3 grid(D_OUT / BN, T_TOK / BM);   // (32, 32)
    moe_tf32_mma_kernel<<<grid, NTHREADS, SMEM_TOTAL>>>(W, bias, experts, out);
}